// round 6
// baseline (speedup 1.0000x reference)
#include <cuda_runtime.h>
#include <cuda_fp16.h>
#include <cstddef>
#include <cstdint>

#define VOCAB 100000
#define NB    16384
#define LSEQ  200
#define EMB   128
#define NCLS  1000

#define ROWS_PER_POOL 8
#define POOL_BLOCKS   (NB / ROWS_PER_POOL)        // 2048
#define MT_ROWS       64
#define N_MT          (NB / MT_ROWS)              // 256
#define POOL_PER_MT   (MT_ROWS / ROWS_PER_POOL)   // 8
#define GEMM_NT       16                          // n-tiles of 64
#define N_TILES       (N_MT * GEMM_NT)            // 4096
#define GEMM_BLOCKS   148                         // one persistent block per SM

// Scratch (alloc-free rule: __device__ globals).
__device__ __align__(16) __half g_table_h[(size_t)VOCAB * EMB];
__device__ __align__(16) __half g_w_h[(size_t)NCLS * EMB];
__device__ __align__(16) __half g_pooled_h[(size_t)NB * EMB];
__device__ int g_cnt[N_MT];

// ---------------------------------------------------------------------------
// Stage 0: convert table AND fc_w fp32 -> fp16; zero the tile counters.
// ---------------------------------------------------------------------------
#define N_TBL4 ((size_t)VOCAB * EMB / 4)
#define N_W4   ((size_t)NCLS * EMB / 4)
#define N_ALL4 (N_TBL4 + N_W4)

__global__ __launch_bounds__(256) void convert_kernel(const float* __restrict__ t,
                                                      const float* __restrict__ W) {
    if (blockIdx.x == 0 && threadIdx.x < N_MT)
        g_cnt[threadIdx.x] = 0;

    const size_t base = (size_t)blockIdx.x * 1024 + threadIdx.x;
    float4 v[4];
    bool   ok[4];
    #pragma unroll
    for (int i = 0; i < 4; ++i) {
        const size_t idx = base + (size_t)i * 256;
        ok[i] = idx < N_ALL4;
        if (ok[i])
            v[i] = (idx < N_TBL4) ? reinterpret_cast<const float4*>(t)[idx]
                                  : reinterpret_cast<const float4*>(W)[idx - N_TBL4];
    }
    #pragma unroll
    for (int i = 0; i < 4; ++i) {
        if (!ok[i]) continue;
        const size_t idx = base + (size_t)i * 256;
        union { __half2 h[2]; uint2 u; } pk;
        pk.h[0] = __floats2half2_rn(v[i].x, v[i].y);
        pk.h[1] = __floats2half2_rn(v[i].z, v[i].w);
        if (idx < N_TBL4) reinterpret_cast<uint2*>(g_table_h)[idx] = pk.u;
        else              reinterpret_cast<uint2*>(g_w_h)[idx - N_TBL4] = pk.u;
    }
}

// ---------------------------------------------------------------------------
// Fused kernel.
// bids [0,148): persistent GEMM workers — resident from launch, loop over
//   64x64 tiles, spin-wait on per-m-tile counters, HMMA, fused-bias store.
// bids [148, 2196): pool blocks (8 rows each, warp per row, depth-4 MLP).
// ---------------------------------------------------------------------------
__device__ __forceinline__ void hacc(float4& a, uint2 u) {
    const float2 f0 = __half22float2(*reinterpret_cast<__half2*>(&u.x));
    const float2 f1 = __half22float2(*reinterpret_cast<__half2*>(&u.y));
    a.x += f0.x; a.y += f0.y; a.z += f1.x; a.w += f1.y;
}

__device__ __forceinline__ void mma16816(float* d,
                                         uint32_t a0, uint32_t a1, uint32_t a2, uint32_t a3,
                                         uint32_t b0, uint32_t b1) {
    asm volatile(
        "mma.sync.aligned.m16n8k16.row.col.f32.f16.f16.f32 "
        "{%0,%1,%2,%3}, {%4,%5,%6,%7}, {%8,%9}, {%0,%1,%2,%3};\n"
        : "+f"(d[0]), "+f"(d[1]), "+f"(d[2]), "+f"(d[3])
        : "r"(a0), "r"(a1), "r"(a2), "r"(a3), "r"(b0), "r"(b1));
}

__device__ __forceinline__ int swz(int row, int chunk) {
    return row * 128 + ((chunk ^ (row & 7)) << 3);
}

__global__ __launch_bounds__(256, 4) void fused_kernel(const int* __restrict__ seq,
                                                       const float* __restrict__ bias,
                                                       float* __restrict__ out) {
    __shared__ union {
        int tok[ROWS_PER_POOL][LSEQ];                          // 6.4 KB (pool)
        struct { __half A[64 * 128]; __half B[64 * 128]; } g;  // 32 KB (gemm)
    } sm;

    const int bid  = blockIdx.x;
    const int tid  = threadIdx.x;
    const int lane = tid & 31;
    const int wid  = tid >> 5;

    if (bid >= GEMM_BLOCKS) {
        // ----------------------- POOL PATH -----------------------
        const int pb = bid - GEMM_BLOCKS;
        const int b0 = pb * ROWS_PER_POOL;

        for (int i = tid; i < ROWS_PER_POOL * LSEQ; i += 256)
            sm.tok[i / LSEQ][i % LSEQ] = seq[(size_t)b0 * LSEQ + i];
        __syncthreads();

        float4 a0 = {0,0,0,0}, a1 = {0,0,0,0}, a2 = {0,0,0,0}, a3 = {0,0,0,0};

        #pragma unroll 2
        for (int l = 0; l < LSEQ; l += 4) {
            const int t0 = sm.tok[wid][l + 0];
            const int t1 = sm.tok[wid][l + 1];
            const int t2 = sm.tok[wid][l + 2];
            const int t3 = sm.tok[wid][l + 3];
            if (t0) hacc(a0, __ldg(reinterpret_cast<const uint2*>(g_table_h + (size_t)t0 * EMB) + lane));
            if (t1) hacc(a1, __ldg(reinterpret_cast<const uint2*>(g_table_h + (size_t)t1 * EMB) + lane));
            if (t2) hacc(a2, __ldg(reinterpret_cast<const uint2*>(g_table_h + (size_t)t2 * EMB) + lane));
            if (t3) hacc(a3, __ldg(reinterpret_cast<const uint2*>(g_table_h + (size_t)t3 * EMB) + lane));
        }

        union { __half2 h[2]; uint2 u; } pk;
        pk.h[0] = __floats2half2_rn((a0.x + a1.x) + (a2.x + a3.x),
                                    (a0.y + a1.y) + (a2.y + a3.y));
        pk.h[1] = __floats2half2_rn((a0.z + a1.z) + (a2.z + a3.z),
                                    (a0.w + a1.w) + (a2.w + a3.w));
        reinterpret_cast<uint2*>(g_pooled_h + (size_t)(b0 + wid) * EMB)[lane] = pk.u;

        __threadfence();
        __syncthreads();
        if (tid == 0) atomicAdd(&g_cnt[pb / POOL_PER_MT], 1);
        return;
    }

    // ------------------- PERSISTENT GEMM PATH -------------------
    const int wm = wid >> 2;   // 0..1 (m, 32 rows)
    const int wn = wid & 3;    // 0..3 (n, 16 cols)
    const int lq = lane >> 2;
    const int lr = lane & 3;

    for (int t = bid; t < N_TILES; t += GEMM_BLOCKS) {
        const int mt = t >> 4;
        const int n0 = (t & 15) * 64;
        const int m0 = mt * MT_ROWS;

        // Acquire this m-tile's pooled rows.
        if (tid == 0) {
            while (atomicOr(&g_cnt[mt], 0) < POOL_PER_MT) __nanosleep(64);
            __threadfence();
        }
        __syncthreads();   // also guards smem reuse from previous iteration

        // Load A and B tiles (64x128 each) into swizzled smem.
        {
            const int r0 = tid >> 4;
            const int c  = tid & 15;
            #pragma unroll
            for (int it = 0; it < 4; ++it) {
                const int r = r0 + it * 16;
                const uint4 va = reinterpret_cast<const uint4*>(
                    g_pooled_h + (size_t)(m0 + r) * EMB)[c];
                *reinterpret_cast<uint4*>(&sm.g.A[swz(r, c)]) = va;
                uint4 vb = make_uint4(0u, 0u, 0u, 0u);
                if (n0 + r < NCLS)
                    vb = reinterpret_cast<const uint4*>(g_w_h + (size_t)(n0 + r) * EMB)[c];
                *reinterpret_cast<uint4*>(&sm.g.B[swz(r, c)]) = vb;
            }
        }
        __syncthreads();

        float acc[2][2][4] = {};

        #pragma unroll
        for (int ks = 0; ks < 8; ++ks) {
            uint32_t a[2][4];
            #pragma unroll
            for (int mi = 0; mi < 2; ++mi) {
                const int r  = wm * 32 + mi * 16 + lq;
                const int o0 = ((2 * ks)     ^ (r & 7)) * 8 + lr * 2;
                const int o1 = ((2 * ks + 1) ^ (r & 7)) * 8 + lr * 2;
                a[mi][0] = *reinterpret_cast<const uint32_t*>(&sm.g.A[r * 128 + o0]);
                a[mi][1] = *reinterpret_cast<const uint32_t*>(&sm.g.A[(r + 8) * 128 + o0]);
                a[mi][2] = *reinterpret_cast<const uint32_t*>(&sm.g.A[r * 128 + o1]);
                a[mi][3] = *reinterpret_cast<const uint32_t*>(&sm.g.A[(r + 8) * 128 + o1]);
            }
            #pragma unroll
            for (int nt = 0; nt < 2; ++nt) {
                const int n  = wn * 16 + nt * 8 + lq;
                const int o0 = ((2 * ks)     ^ (n & 7)) * 8 + lr * 2;
                const int o1 = ((2 * ks + 1) ^ (n & 7)) * 8 + lr * 2;
                const uint32_t b0 = *reinterpret_cast<const uint32_t*>(&sm.g.B[n * 128 + o0]);
                const uint32_t b1 = *reinterpret_cast<const uint32_t*>(&sm.g.B[n * 128 + o1]);
                #pragma unroll
                for (int mi = 0; mi < 2; ++mi)
                    mma16816(acc[mi][nt], a[mi][0], a[mi][1], a[mi][2], a[mi][3], b0, b1);
            }
        }

        // Epilogue: fused bias, predicated float2 stores.
        #pragma unroll
        for (int nt = 0; nt < 2; ++nt) {
            const int n = n0 + wn * 16 + nt * 8 + lr * 2;
            if (n < NCLS) {
                const float2 b2 = *reinterpret_cast<const float2*>(bias + n);
                #pragma unroll
                for (int mi = 0; mi < 2; ++mi) {
                    const int m = m0 + wm * 32 + mi * 16 + lq;
                    float2 r0, r1;
                    r0.x = acc[mi][nt][0] + b2.x;
                    r0.y = acc[mi][nt][1] + b2.y;
                    r1.x = acc[mi][nt][2] + b2.x;
                    r1.y = acc[mi][nt][3] + b2.y;
                    *reinterpret_cast<float2*>(out + (size_t)m * NCLS + n)       = r0;
                    *reinterpret_cast<float2*>(out + (size_t)(m + 8) * NCLS + n) = r1;
                }
            }
        }
        __syncthreads();   // all LDS done before next iteration overwrites smem
    }
}

extern "C" void kernel_launch(void* const* d_in, const int* in_sizes, int n_in,
                              void* d_out, int out_size) {
    const int*   seq   = (const int*)d_in[0];
    const float* table = (const float*)d_in[1];
    const float* W     = (const float*)d_in[2];
    const float* bias  = (const float*)d_in[3];
    float*       out   = (float*)d_out;

    const int conv_blocks = (int)((N_ALL4 + 1023) / 1024);
    convert_kernel<<<conv_blocks, 256>>>(table, W);

    fused_kernel<<<GEMM_BLOCKS + POOL_BLOCKS, 256>>>(seq, bias, out);
}

// round 7
// speedup vs baseline: 1.2458x; 1.2458x over previous
#include <cuda_runtime.h>
#include <cuda_fp16.h>
#include <cstddef>
#include <cstdint>

#define VOCAB 100000
#define NB    16384
#define LSEQ  200
#define EMB   128
#define NCLS  1000

// Scratch (alloc-free rule: __device__ globals).
__device__ __align__(16) __half g_table_h[(size_t)VOCAB * EMB];   // 25.6 MB
__device__ __align__(16) __half g_w_h[(size_t)NCLS * EMB];        // 256 KB
__device__ __align__(16) __half g_pooled_h[(size_t)NB * EMB];     // 4 MB

// ---------------------------------------------------------------------------
// Stage 0: convert table AND fc_w fp32 -> fp16. 4 independent float4 per
// thread (MLP_p1 = 4) to cover DRAM latency. (Profiled: 12.3 us.)
// ---------------------------------------------------------------------------
#define N_TBL4 ((size_t)VOCAB * EMB / 4)   // 3,200,000 float4
#define N_W4   ((size_t)NCLS * EMB / 4)    //    32,000 float4
#define N_ALL4 (N_TBL4 + N_W4)

__global__ __launch_bounds__(256) void convert_kernel(const float* __restrict__ t,
                                                      const float* __restrict__ W) {
    const size_t base = (size_t)blockIdx.x * 1024 + threadIdx.x;
    float4 v[4];
    bool   ok[4];
    #pragma unroll
    for (int i = 0; i < 4; ++i) {
        const size_t idx = base + (size_t)i * 256;
        ok[i] = idx < N_ALL4;
        if (ok[i])
            v[i] = (idx < N_TBL4) ? reinterpret_cast<const float4*>(t)[idx]
                                  : reinterpret_cast<const float4*>(W)[idx - N_TBL4];
    }
    #pragma unroll
    for (int i = 0; i < 4; ++i) {
        if (!ok[i]) continue;
        const size_t idx = base + (size_t)i * 256;
        union { __half2 h[2]; uint2 u; } pk;
        pk.h[0] = __floats2half2_rn(v[i].x, v[i].y);
        pk.h[1] = __floats2half2_rn(v[i].z, v[i].w);
        if (idx < N_TBL4) reinterpret_cast<uint2*>(g_table_h)[idx] = pk.u;
        else              reinterpret_cast<uint2*>(g_w_h)[idx - N_TBL4] = pk.u;
    }
}

// ---------------------------------------------------------------------------
// Stage 1: masked embedding-bag sum pool — EXACT R3 version (proven, at the
// chip LTS cap). One warp per batch row; lane owns 4 dims (uint2 loads).
// ---------------------------------------------------------------------------
__device__ __forceinline__ void hacc(float4& a, uint2 u) {
    const float2 f0 = __half22float2(*reinterpret_cast<__half2*>(&u.x));
    const float2 f1 = __half22float2(*reinterpret_cast<__half2*>(&u.y));
    a.x += f0.x; a.y += f0.y; a.z += f1.x; a.w += f1.y;
}

__global__ __launch_bounds__(256) void pool_kernel(const int* __restrict__ seq) {
    __shared__ int s_tok[8][LSEQ];
    const int wid  = threadIdx.x >> 5;
    const int lane = threadIdx.x & 31;
    const int b0   = blockIdx.x * 8;

    for (int i = threadIdx.x; i < 8 * LSEQ; i += 256)
        s_tok[i / LSEQ][i % LSEQ] = seq[(size_t)b0 * LSEQ + i];
    __syncthreads();

    float4 a0 = {0,0,0,0}, a1 = {0,0,0,0}, a2 = {0,0,0,0}, a3 = {0,0,0,0};

    #pragma unroll 2
    for (int l = 0; l < LSEQ; l += 4) {
        const int t0 = s_tok[wid][l + 0];
        const int t1 = s_tok[wid][l + 1];
        const int t2 = s_tok[wid][l + 2];
        const int t3 = s_tok[wid][l + 3];
        if (t0) hacc(a0, reinterpret_cast<const uint2*>(g_table_h + (size_t)t0 * EMB)[lane]);
        if (t1) hacc(a1, reinterpret_cast<const uint2*>(g_table_h + (size_t)t1 * EMB)[lane]);
        if (t2) hacc(a2, reinterpret_cast<const uint2*>(g_table_h + (size_t)t2 * EMB)[lane]);
        if (t3) hacc(a3, reinterpret_cast<const uint2*>(g_table_h + (size_t)t3 * EMB)[lane]);
    }

    union { __half2 h[2]; uint2 u; } pk;
    pk.h[0] = __floats2half2_rn((a0.x + a1.x) + (a2.x + a3.x),
                                (a0.y + a1.y) + (a2.y + a3.y));
    pk.h[1] = __floats2half2_rn((a0.z + a1.z) + (a2.z + a3.z),
                                (a0.w + a1.w) + (a2.w + a3.w));
    reinterpret_cast<uint2*>(g_pooled_h + (size_t)(b0 + wid) * EMB)[lane] = pk.u;
}

// ---------------------------------------------------------------------------
// Stage 2: HMMA GEMM. Block computes a 128(m) x 128(n) output via TWO
// sequential 64-wide n-passes that share one A tile (halves A L2 traffic
// vs 64-wide blocks). K=128 resident. 48 KB static smem -> 4 blocks/SM.
// 8 warps as 4(m) x 2(n); warp tile 32x32 per pass; acc = 32 floats.
// ---------------------------------------------------------------------------
__device__ __forceinline__ void mma16816(float* d,
                                         uint32_t a0, uint32_t a1, uint32_t a2, uint32_t a3,
                                         uint32_t b0, uint32_t b1) {
    asm volatile(
        "mma.sync.aligned.m16n8k16.row.col.f32.f16.f16.f32 "
        "{%0,%1,%2,%3}, {%4,%5,%6,%7}, {%8,%9}, {%0,%1,%2,%3};\n"
        : "+f"(d[0]), "+f"(d[1]), "+f"(d[2]), "+f"(d[3])
        : "r"(a0), "r"(a1), "r"(a2), "r"(a3), "r"(b0), "r"(b1));
}

// smem half-index with 16B-chunk XOR swizzle (row = 128 halfs = 16 chunks).
__device__ __forceinline__ int swz(int row, int chunk) {
    return row * 128 + ((chunk ^ (row & 7)) << 3);
}

__global__ __launch_bounds__(256) void gemm_kernel(const float* __restrict__ bias,
                                                   float* __restrict__ out) {
    __shared__ __half sA[128 * 128];   // 32 KB
    __shared__ __half sB[64 * 128];    // 16 KB (reloaded between passes)

    const int tid  = threadIdx.x;
    const int lane = tid & 31;
    const int wid  = tid >> 5;
    const int wm   = wid >> 1;         // 0..3 (m, 32 rows each)
    const int wn   = wid & 1;          // 0..1 (n, 32 cols each)
    const int m0   = blockIdx.x * 128;
    const int nb0  = blockIdx.y * 128;

    const int lq = lane >> 2;          // 0..7
    const int lr = lane & 3;           // 0..3
    const int r0 = tid >> 4;           // 0..15 (loader row)
    const int c  = tid & 15;           // loader chunk

    // Load the shared A tile once: 128 rows x 16 chunks.
    #pragma unroll
    for (int it = 0; it < 8; ++it) {
        const int r = r0 + it * 16;
        const uint4 v = reinterpret_cast<const uint4*>(
            g_pooled_h + (size_t)(m0 + r) * EMB)[c];
        *reinterpret_cast<uint4*>(&sA[swz(r, c)]) = v;
    }

    #pragma unroll
    for (int p = 0; p < 2; ++p) {
        const int n0 = nb0 + p * 64;

        // Load this pass's B half: 64 rows x 16 chunks (>= NCLS zero-filled).
        if (p) __syncthreads();   // all warps done reading previous B half
        #pragma unroll
        for (int it = 0; it < 4; ++it) {
            const int r = r0 + it * 16;
            uint4 v = make_uint4(0u, 0u, 0u, 0u);
            if (n0 + r < NCLS)
                v = reinterpret_cast<const uint4*>(g_w_h + (size_t)(n0 + r) * EMB)[c];
            *reinterpret_cast<uint4*>(&sB[swz(r, c)]) = v;
        }
        __syncthreads();

        float acc[2][4][4] = {};

        #pragma unroll
        for (int ks = 0; ks < 8; ++ks) {
            uint32_t a[2][4];
            #pragma unroll
            for (int mi = 0; mi < 2; ++mi) {
                const int r  = wm * 32 + mi * 16 + lq;
                const int o0 = ((2 * ks)     ^ (r & 7)) * 8 + lr * 2;
                const int o1 = ((2 * ks + 1) ^ (r & 7)) * 8 + lr * 2;
                a[mi][0] = *reinterpret_cast<const uint32_t*>(&sA[r * 128 + o0]);
                a[mi][1] = *reinterpret_cast<const uint32_t*>(&sA[(r + 8) * 128 + o0]);
                a[mi][2] = *reinterpret_cast<const uint32_t*>(&sA[r * 128 + o1]);
                a[mi][3] = *reinterpret_cast<const uint32_t*>(&sA[(r + 8) * 128 + o1]);
            }
            #pragma unroll
            for (int nt = 0; nt < 4; ++nt) {
                const int n  = wn * 32 + nt * 8 + lq;
                const int o0 = ((2 * ks)     ^ (n & 7)) * 8 + lr * 2;
                const int o1 = ((2 * ks + 1) ^ (n & 7)) * 8 + lr * 2;
                const uint32_t b0 = *reinterpret_cast<const uint32_t*>(&sB[n * 128 + o0]);
                const uint32_t b1 = *reinterpret_cast<const uint32_t*>(&sB[n * 128 + o1]);
                #pragma unroll
                for (int mi = 0; mi < 2; ++mi)
                    mma16816(acc[mi][nt], a[mi][0], a[mi][1], a[mi][2], a[mi][3], b0, b1);
            }
        }

        // Epilogue for this pass: fused bias, predicated float2 stores.
        #pragma unroll
        for (int nt = 0; nt < 4; ++nt) {
            const int n = n0 + wn * 32 + nt * 8 + lr * 2;
            if (n < NCLS) {
                const float2 b2 = *reinterpret_cast<const float2*>(bias + n);
                #pragma unroll
                for (int mi = 0; mi < 2; ++mi) {
                    const int m = m0 + wm * 32 + mi * 16 + lq;
                    float2 s0, s1;
                    s0.x = acc[mi][nt][0] + b2.x;
                    s0.y = acc[mi][nt][1] + b2.y;
                    s1.x = acc[mi][nt][2] + b2.x;
                    s1.y = acc[mi][nt][3] + b2.y;
                    *reinterpret_cast<float2*>(out + (size_t)m * NCLS + n)       = s0;
                    *reinterpret_cast<float2*>(out + (size_t)(m + 8) * NCLS + n) = s1;
                }
            }
        }
    }
}

extern "C" void kernel_launch(void* const* d_in, const int* in_sizes, int n_in,
                              void* d_out, int out_size) {
    const int*   seq   = (const int*)d_in[0];
    const float* table = (const float*)d_in[1];
    const float* W     = (const float*)d_in[2];
    const float* bias  = (const float*)d_in[3];
    float*       out   = (float*)d_out;

    const int conv_blocks = (int)((N_ALL4 + 1023) / 1024);
    convert_kernel<<<conv_blocks, 256>>>(table, W);

    pool_kernel<<<NB / 8, 256>>>(seq);

    dim3 grid(NB / 128, (NCLS + 127) / 128);   // 128 x 8
    gemm_kernel<<<grid, 256>>>(bias, out);
}

// round 8
// speedup vs baseline: 1.2466x; 1.0006x over previous
#include <cuda_runtime.h>
#include <cuda_fp16.h>
#include <cstddef>
#include <cstdint>

#define VOCAB 100000
#define NB    16384
#define LSEQ  200
#define EMB   128
#define NCLS  1000

// Scratch (alloc-free rule: __device__ globals).
__device__ __align__(16) __half g_table_h[(size_t)VOCAB * EMB];   // 25.6 MB
__device__ __align__(16) __half g_w_h[(size_t)NCLS * EMB];        // 256 KB
__device__ __align__(16) __half g_pooled_h[(size_t)NB * EMB];     // 4 MB

// ---------------------------------------------------------------------------
// Stage 0: convert table AND fc_w fp32 -> fp16.
// 8 independent float4 loads per thread (MLP_p1 = 8) to cover DRAM latency;
// __ldcs on the fp32 source (read-once) so it doesn't evict the freshly
// written fp16 table from L2 before the pool consumes it.
// ---------------------------------------------------------------------------
#define N_TBL4 ((size_t)VOCAB * EMB / 4)   // 3,200,000 float4
#define N_W4   ((size_t)NCLS * EMB / 4)    //    32,000 float4
#define N_ALL4 (N_TBL4 + N_W4)
#define CONV_PER_BLK 2048                  // 256 threads x 8 float4
#define CONV_BLOCKS  ((int)((N_ALL4 + CONV_PER_BLK - 1) / CONV_PER_BLK))

__global__ __launch_bounds__(256) void convert_kernel(const float* __restrict__ t,
                                                      const float* __restrict__ W) {
    const size_t base = (size_t)blockIdx.x * CONV_PER_BLK + threadIdx.x;
    float4 v[8];
    bool   ok[8];
    #pragma unroll
    for (int i = 0; i < 8; ++i) {
        const size_t idx = base + (size_t)i * 256;
        ok[i] = idx < N_ALL4;
        if (ok[i]) {
            const float4* src = (idx < N_TBL4)
                ? reinterpret_cast<const float4*>(t) + idx
                : reinterpret_cast<const float4*>(W) + (idx - N_TBL4);
            v[i] = __ldcs(src);   // streaming: evict-first in L2
        }
    }
    #pragma unroll
    for (int i = 0; i < 8; ++i) {
        if (!ok[i]) continue;
        const size_t idx = base + (size_t)i * 256;
        union { __half2 h[2]; uint2 u; } pk;
        pk.h[0] = __floats2half2_rn(v[i].x, v[i].y);
        pk.h[1] = __floats2half2_rn(v[i].z, v[i].w);
        if (idx < N_TBL4) reinterpret_cast<uint2*>(g_table_h)[idx] = pk.u;
        else              reinterpret_cast<uint2*>(g_w_h)[idx - N_TBL4] = pk.u;
    }
}

// ---------------------------------------------------------------------------
// Stage 1: masked embedding-bag sum pool — EXACT R3 version (proven, at the
// chip LTS cap). One warp per batch row; lane owns 4 dims (uint2 loads).
// ---------------------------------------------------------------------------
__device__ __forceinline__ void hacc(float4& a, uint2 u) {
    const float2 f0 = __half22float2(*reinterpret_cast<__half2*>(&u.x));
    const float2 f1 = __half22float2(*reinterpret_cast<__half2*>(&u.y));
    a.x += f0.x; a.y += f0.y; a.z += f1.x; a.w += f1.y;
}

__global__ __launch_bounds__(256) void pool_kernel(const int* __restrict__ seq) {
    __shared__ int s_tok[8][LSEQ];
    const int wid  = threadIdx.x >> 5;
    const int lane = threadIdx.x & 31;
    const int b0   = blockIdx.x * 8;

    for (int i = threadIdx.x; i < 8 * LSEQ; i += 256)
        s_tok[i / LSEQ][i % LSEQ] = seq[(size_t)b0 * LSEQ + i];
    __syncthreads();

    float4 a0 = {0,0,0,0}, a1 = {0,0,0,0}, a2 = {0,0,0,0}, a3 = {0,0,0,0};

    #pragma unroll 2
    for (int l = 0; l < LSEQ; l += 4) {
        const int t0 = s_tok[wid][l + 0];
        const int t1 = s_tok[wid][l + 1];
        const int t2 = s_tok[wid][l + 2];
        const int t3 = s_tok[wid][l + 3];
        if (t0) hacc(a0, reinterpret_cast<const uint2*>(g_table_h + (size_t)t0 * EMB)[lane]);
        if (t1) hacc(a1, reinterpret_cast<const uint2*>(g_table_h + (size_t)t1 * EMB)[lane]);
        if (t2) hacc(a2, reinterpret_cast<const uint2*>(g_table_h + (size_t)t2 * EMB)[lane]);
        if (t3) hacc(a3, reinterpret_cast<const uint2*>(g_table_h + (size_t)t3 * EMB)[lane]);
    }

    union { __half2 h[2]; uint2 u; } pk;
    pk.h[0] = __floats2half2_rn((a0.x + a1.x) + (a2.x + a3.x),
                                (a0.y + a1.y) + (a2.y + a3.y));
    pk.h[1] = __floats2half2_rn((a0.z + a1.z) + (a2.z + a3.z),
                                (a0.w + a1.w) + (a2.w + a3.w));
    reinterpret_cast<uint2*>(g_pooled_h + (size_t)(b0 + wid) * EMB)[lane] = pk.u;
}

// ---------------------------------------------------------------------------
// Stage 2: HMMA GEMM — EXACT R7 version (at its store/launch floor).
// Block computes 128x128 output via two 64-wide n-passes sharing one A tile.
// ---------------------------------------------------------------------------
__device__ __forceinline__ void mma16816(float* d,
                                         uint32_t a0, uint32_t a1, uint32_t a2, uint32_t a3,
                                         uint32_t b0, uint32_t b1) {
    asm volatile(
        "mma.sync.aligned.m16n8k16.row.col.f32.f16.f16.f32 "
        "{%0,%1,%2,%3}, {%4,%5,%6,%7}, {%8,%9}, {%0,%1,%2,%3};\n"
        : "+f"(d[0]), "+f"(d[1]), "+f"(d[2]), "+f"(d[3])
        : "r"(a0), "r"(a1), "r"(a2), "r"(a3), "r"(b0), "r"(b1));
}

__device__ __forceinline__ int swz(int row, int chunk) {
    return row * 128 + ((chunk ^ (row & 7)) << 3);
}

__global__ __launch_bounds__(256) void gemm_kernel(const float* __restrict__ bias,
                                                   float* __restrict__ out) {
    __shared__ __half sA[128 * 128];   // 32 KB
    __shared__ __half sB[64 * 128];    // 16 KB (reloaded between passes)

    const int tid  = threadIdx.x;
    const int lane = tid & 31;
    const int wid  = tid >> 5;
    const int wm   = wid >> 1;         // 0..3 (m, 32 rows each)
    const int wn   = wid & 1;          // 0..1 (n, 32 cols each)
    const int m0   = blockIdx.x * 128;
    const int nb0  = blockIdx.y * 128;

    const int lq = lane >> 2;
    const int lr = lane & 3;
    const int r0 = tid >> 4;
    const int c  = tid & 15;

    #pragma unroll
    for (int it = 0; it < 8; ++it) {
        const int r = r0 + it * 16;
        const uint4 v = reinterpret_cast<const uint4*>(
            g_pooled_h + (size_t)(m0 + r) * EMB)[c];
        *reinterpret_cast<uint4*>(&sA[swz(r, c)]) = v;
    }

    #pragma unroll
    for (int p = 0; p < 2; ++p) {
        const int n0 = nb0 + p * 64;

        if (p) __syncthreads();
        #pragma unroll
        for (int it = 0; it < 4; ++it) {
            const int r = r0 + it * 16;
            uint4 v = make_uint4(0u, 0u, 0u, 0u);
            if (n0 + r < NCLS)
                v = reinterpret_cast<const uint4*>(g_w_h + (size_t)(n0 + r) * EMB)[c];
            *reinterpret_cast<uint4*>(&sB[swz(r, c)]) = v;
        }
        __syncthreads();

        float acc[2][4][4] = {};

        #pragma unroll
        for (int ks = 0; ks < 8; ++ks) {
            uint32_t a[2][4];
            #pragma unroll
            for (int mi = 0; mi < 2; ++mi) {
                const int r  = wm * 32 + mi * 16 + lq;
                const int o0 = ((2 * ks)     ^ (r & 7)) * 8 + lr * 2;
                const int o1 = ((2 * ks + 1) ^ (r & 7)) * 8 + lr * 2;
                a[mi][0] = *reinterpret_cast<const uint32_t*>(&sA[r * 128 + o0]);
                a[mi][1] = *reinterpret_cast<const uint32_t*>(&sA[(r + 8) * 128 + o0]);
                a[mi][2] = *reinterpret_cast<const uint32_t*>(&sA[r * 128 + o1]);
                a[mi][3] = *reinterpret_cast<const uint32_t*>(&sA[(r + 8) * 128 + o1]);
            }
            #pragma unroll
            for (int nt = 0; nt < 4; ++nt) {
                const int n  = wn * 32 + nt * 8 + lq;
                const int o0 = ((2 * ks)     ^ (n & 7)) * 8 + lr * 2;
                const int o1 = ((2 * ks + 1) ^ (n & 7)) * 8 + lr * 2;
                const uint32_t b0 = *reinterpret_cast<const uint32_t*>(&sB[n * 128 + o0]);
                const uint32_t b1 = *reinterpret_cast<const uint32_t*>(&sB[n * 128 + o1]);
                #pragma unroll
                for (int mi = 0; mi < 2; ++mi)
                    mma16816(acc[mi][nt], a[mi][0], a[mi][1], a[mi][2], a[mi][3], b0, b1);
            }
        }

        #pragma unroll
        for (int nt = 0; nt < 4; ++nt) {
            const int n = n0 + wn * 32 + nt * 8 + lr * 2;
            if (n < NCLS) {
                const float2 b2 = *reinterpret_cast<const float2*>(bias + n);
                #pragma unroll
                for (int mi = 0; mi < 2; ++mi) {
                    const int m = m0 + wm * 32 + mi * 16 + lq;
                    float2 s0, s1;
                    s0.x = acc[mi][nt][0] + b2.x;
                    s0.y = acc[mi][nt][1] + b2.y;
                    s1.x = acc[mi][nt][2] + b2.x;
                    s1.y = acc[mi][nt][3] + b2.y;
                    *reinterpret_cast<float2*>(out + (size_t)m * NCLS + n)       = s0;
                    *reinterpret_cast<float2*>(out + (size_t)(m + 8) * NCLS + n) = s1;
                }
            }
        }
    }
}

extern "C" void kernel_launch(void* const* d_in, const int* in_sizes, int n_in,
                              void* d_out, int out_size) {
    const int*   seq   = (const int*)d_in[0];
    const float* table = (const float*)d_in[1];
    const float* W     = (const float*)d_in[2];
    const float* bias  = (const float*)d_in[3];
    float*       out   = (float*)d_out;

    convert_kernel<<<CONV_BLOCKS, 256>>>(table, W);

    pool_kernel<<<NB / 8, 256>>>(seq);

    dim3 grid(NB / 128, (NCLS + 127) / 128);   // 128 x 8
    gemm_kernel<<<grid, 256>>>(bias, out);
}